// round 1
// baseline (speedup 1.0000x reference)
#include <cuda_runtime.h>
#include <math.h>

// ---------------- problem constants ----------------
#define BATCH 4
#define CF    64        // feature channels (half-res input)
#define HH    128       // half-res H
#define WHALF 128       // half-res W
#define H     256
#define W     256
#define KT    51        // separable taps / conv channels
#define OCP   52        // padded output channels (52 = 13 float4)
#define NB    4         // kernel branches (k1v,k1h,k2v,k2h)
#define PADI  25        // (KT-1)/2
#define IMGW  306       // W + 2*PADI
#define HW    (H*W)

// ---------------- scratch (device globals; no allocation allowed) ----------
__device__ float g_u  [BATCH*CF*HW];        // upsampled features
__device__ float g_h1 [BATCH*NB*KT*HW];     // conv1 out
__device__ float g_h2 [BATCH*NB*KT*HW];     // conv2 out
__device__ float g_h3 [BATCH*NB*KT*HW];     // conv3 out (the 4 kernel maps)
__device__ float g_w1t[NB*CF*9*OCP];        // transposed/padded weights
__device__ float g_w2t[NB*KT*9*OCP];
__device__ float g_w3t[NB*KT*9*OCP];

// ---------------- 2x bilinear upsample, align_corners=True ----------------
__global__ void upsample_k(const float* __restrict__ x)
{
    int idx = blockIdx.x * blockDim.x + threadIdx.x;
    const int total = BATCH*CF*HW;
    if (idx >= total) return;
    int xo = idx % W;
    int t  = idx / W;
    int yo = t % H;
    t      = t / H;      // t = b*CF + c

    const float s = (float)(HH - 1) / (float)(H - 1);   // 127/255
    float fy = (float)yo * s;
    int   ly = (int)floorf(fy);
    float wy = fy - (float)ly;
    int   hy = min(ly + 1, HH - 1);
    float fx = (float)xo * s;
    int   lx = (int)floorf(fx);
    float wx = fx - (float)lx;
    int   hx = min(lx + 1, WHALF - 1);

    const float* xp = x + (size_t)t * HH * WHALF;
    float a = xp[ly*WHALF + lx];
    float b = xp[hy*WHALF + lx];
    float c = xp[ly*WHALF + hx];
    float d = xp[hy*WHALF + hx];
    float col0 = a*(1.f-wy) + b*wy;     // H-lerp first (matches reference order)
    float col1 = c*(1.f-wy) + d*wy;
    g_u[idx] = col0*(1.f-wx) + col1*wx; // then W-lerp
}

// ------------- weight transpose:  [g*KT+oc][ic][3][3] -> [g][ic][tap][OCP] --
__global__ void wprep_k(const float* __restrict__ w, float* __restrict__ wt, int cin)
{
    int idx = blockIdx.x * blockDim.x + threadIdx.x;
    int total = NB * cin * 9 * OCP;
    if (idx >= total) return;
    int oc  = idx % OCP;
    int t   = idx / OCP;
    int tap = t % 9;
    t       = t / 9;
    int ic  = t % cin;
    int g   = t / cin;
    float v = 0.f;
    if (oc < KT) v = w[(((size_t)(g*KT + oc) * cin + ic) * 9) + tap];
    wt[idx] = v;
}

// ---------------- conv3x3 + bias + relu -----------------------------------
// CIN = input channels per group. GROUPED=false: all groups read same CIN
// input channels (conv1). GROUPED=true: group g reads channels [g*CIN, ...).
// grid: (W/16, H/16, BATCH*NB); block 256 = 16x16 pixels; each thread owns
// all OCP output-channel accumulators for its pixel.
template<int CIN, bool GROUPED>
__global__ __launch_bounds__(256, 2)
void conv3x3_k(const float* __restrict__ in, const float* __restrict__ wt,
               const float* __restrict__ bias, float* __restrict__ out)
{
    constexpr int ICB = 8;
    __shared__ float s_in[ICB][18][18];
    __shared__ float s_w [ICB * 9 * OCP];

    const int tx = threadIdx.x & 15;
    const int ty = threadIdx.x >> 4;
    const int x0 = blockIdx.x * 16;
    const int y0 = blockIdx.y * 16;
    const int bz = blockIdx.z;
    const int g  = bz % NB;
    const int b  = bz / NB;

    const float* inb = GROUPED
        ? in + ((size_t)b * NB * CIN + (size_t)g * CIN) * HW
        : in + (size_t)b * CIN * HW;
    const float* wg = wt + (size_t)g * CIN * 9 * OCP;

    float acc[OCP];
#pragma unroll
    for (int o = 0; o < OCP; o++)
        acc[o] = (o < KT) ? bias[g*KT + o] : 0.f;

    for (int ic0 = 0; ic0 < CIN; ic0 += ICB) {
        const int icb = (CIN - ic0 < ICB) ? (CIN - ic0) : ICB;
        __syncthreads();
        // stage input tile (with 1-px halo, zero padded)
        for (int li = threadIdx.x; li < icb*18*18; li += 256) {
            int p  = li % (18*18);
            int ic = li / (18*18);
            int iy = p / 18, ix = p % 18;
            int gy = y0 + iy - 1, gx = x0 + ix - 1;
            float v = 0.f;
            if (gy >= 0 && gy < H && gx >= 0 && gx < W)
                v = inb[(size_t)(ic0+ic)*HW + (size_t)gy*W + gx];
            s_in[ic][iy][ix] = v;
        }
        // stage weight chunk (contiguous, float4)
        {
            const float4* ws = (const float4*)(wg + (size_t)ic0 * 9 * OCP);
            float4* sd = (float4*)s_w;
            const int nf4 = icb * 9 * (OCP/4);
            for (int li = threadIdx.x; li < nf4; li += 256) sd[li] = ws[li];
        }
        __syncthreads();

        for (int ic = 0; ic < icb; ic++) {
#pragma unroll
            for (int ky = 0; ky < 3; ky++) {
#pragma unroll
                for (int kx = 0; kx < 3; kx++) {
                    float rin = s_in[ic][ty+ky][tx+kx];
                    const float4* wrow = (const float4*)&s_w[(ic*9 + ky*3 + kx) * OCP];
#pragma unroll
                    for (int o4 = 0; o4 < OCP/4; o4++) {
                        float4 wv = wrow[o4];
                        acc[o4*4+0] = fmaf(rin, wv.x, acc[o4*4+0]);
                        acc[o4*4+1] = fmaf(rin, wv.y, acc[o4*4+1]);
                        acc[o4*4+2] = fmaf(rin, wv.z, acc[o4*4+2]);
                        acc[o4*4+3] = fmaf(rin, wv.w, acc[o4*4+3]);
                    }
                }
            }
        }
    }

    size_t ob = ((size_t)b * NB * KT + (size_t)g * KT) * HW
              + (size_t)(y0 + ty) * W + (x0 + tx);
#pragma unroll
    for (int o = 0; o < KT; o++)
        out[ob + (size_t)o * HW] = fmaxf(acc[o], 0.f);
}

// ---------------- separable 51-tap conv + sum of the two frames -----------
// out[b,c,y,x] = sum_j kh[j] * (sum_i kv[i] * img[b,c,y+i,x+j])   (per frame)
// grid: (16,16,BATCH); block 256 = 16x16. 66x66 img tile in smem (rows padded
// to 80 floats -> warp-half rows on disjoint bank groups). v[51] in registers.
__global__ __launch_bounds__(256, 2)
void sepconv_k(const float* __restrict__ i1, const float* __restrict__ i2,
               float* __restrict__ out)
{
    __shared__ float s_img[66 * 80];
    const int tx = threadIdx.x & 15;
    const int ty = threadIdx.x >> 4;
    const int x0 = blockIdx.x * 16;
    const int y0 = blockIdx.y * 16;
    const int b  = blockIdx.z;
    const int y  = y0 + ty, x = x0 + tx;

    const float* kbase = g_h3 + (size_t)b * NB * KT * HW + (size_t)y * W + x;
    float acc[3] = {0.f, 0.f, 0.f};

    for (int im = 0; im < 2; im++) {
        const float* img = im ? i2 : i1;
        const float* kv = kbase + (size_t)(im*2    ) * KT * HW;  // branch 0 / 2
        const float* kh = kbase + (size_t)(im*2 + 1) * KT * HW;  // branch 1 / 3

        for (int c = 0; c < 3; c++) {
            __syncthreads();
            const float* ib = img + ((size_t)b * 3 + c) * IMGW * IMGW;
            for (int li = threadIdx.x; li < 66*66; li += 256) {
                int iy = li / 66, ix = li % 66;
                s_img[iy*80 + ix] = ib[(size_t)(y0 + iy) * IMGW + (x0 + ix)];
            }
            __syncthreads();

            float v[KT];
#pragma unroll
            for (int j = 0; j < KT; j++) v[j] = 0.f;

            for (int i = 0; i < KT; i++) {
                float kvi = kv[(size_t)i * HW];
                const float* srow = &s_img[(ty + i) * 80 + tx];
#pragma unroll
                for (int j = 0; j < KT; j++)
                    v[j] = fmaf(kvi, srow[j], v[j]);
            }
            float o = 0.f;
            for (int j = 0; j < KT; j++)
                o = fmaf(kh[(size_t)j * HW], v[j], o);
            acc[c] += o;
        }
    }

    size_t ob = (size_t)b * 3 * HW + (size_t)y * W + x;
#pragma unroll
    for (int c = 0; c < 3; c++)
        out[ob + (size_t)c * HW] = acc[c];
}

// ---------------- launch ---------------------------------------------------
extern "C" void kernel_launch(void* const* d_in, const int* in_sizes, int n_in,
                              void* d_out, int out_size)
{
    const float* x  = (const float*)d_in[0];
    const float* i1 = (const float*)d_in[1];
    const float* i2 = (const float*)d_in[2];
    const float* W1 = (const float*)d_in[3];
    const float* B1 = (const float*)d_in[4];
    const float* W2 = (const float*)d_in[5];
    const float* B2 = (const float*)d_in[6];
    const float* W3 = (const float*)d_in[7];
    const float* B3 = (const float*)d_in[8];
    float* out = (float*)d_out;

    float *u, *h1, *h2, *h3, *w1t, *w2t, *w3t;
    cudaGetSymbolAddress((void**)&u,   g_u);
    cudaGetSymbolAddress((void**)&h1,  g_h1);
    cudaGetSymbolAddress((void**)&h2,  g_h2);
    cudaGetSymbolAddress((void**)&h3,  g_h3);
    cudaGetSymbolAddress((void**)&w1t, g_w1t);
    cudaGetSymbolAddress((void**)&w2t, g_w2t);
    cudaGetSymbolAddress((void**)&w3t, g_w3t);

    // weight transpose (tiny)
    {
        int n1 = NB*CF*9*OCP, n2 = NB*KT*9*OCP;
        wprep_k<<<(n1 + 255)/256, 256>>>(W1, w1t, CF);
        wprep_k<<<(n2 + 255)/256, 256>>>(W2, w2t, KT);
        wprep_k<<<(n2 + 255)/256, 256>>>(W3, w3t, KT);
    }

    // upsample
    {
        int n = BATCH*CF*HW;
        upsample_k<<<(n + 255)/256, 256>>>(x);
    }

    dim3 cgrid(W/16, H/16, BATCH*NB);
    dim3 cblk(256);
    conv3x3_k<CF, false><<<cgrid, cblk>>>(u,  w1t, B1, h1);
    conv3x3_k<KT, true ><<<cgrid, cblk>>>(h1, w2t, B2, h2);
    conv3x3_k<KT, true ><<<cgrid, cblk>>>(h2, w3t, B3, h3);

    dim3 sgrid(W/16, H/16, BATCH);
    sepconv_k<<<sgrid, cblk>>>(i1, i2, out);

    (void)in_sizes; (void)n_in; (void)out_size;
}

// round 4
// speedup vs baseline: 1.0241x; 1.0241x over previous
#include <cuda_runtime.h>
#include <math.h>

// ---------------- problem constants ----------------
#define BATCH 4
#define CF    64        // feature channels (half-res input)
#define HH    128       // half-res H
#define WHALF 128       // half-res W
#define H     256
#define W     256
#define KT    51        // separable taps / conv channels
#define OCP   52        // padded output channels (52 = 13 float4 = 26 f32x2)
#define NB    4         // kernel branches (k1v,k1h,k2v,k2h)
#define PADI  25        // (KT-1)/2
#define IMGW  306       // W + 2*PADI
#define HW    (H*W)

typedef unsigned long long u64;

// ---------------- packed f32x2 helpers (sm_100+) ---------------------------
__device__ __forceinline__ u64 pack2(float lo, float hi) {
    u64 r;
    asm("mov.b64 %0, {%1, %2};" : "=l"(r) : "f"(lo), "f"(hi));
    return r;
}
__device__ __forceinline__ void unpack2(u64 v, float& lo, float& hi) {
    asm("mov.b64 {%0, %1}, %2;" : "=f"(lo), "=f"(hi) : "l"(v));
}
__device__ __forceinline__ void fma2(u64& acc, u64 a, u64 b) {
    asm("fma.rn.f32x2 %0, %1, %2, %0;" : "+l"(acc) : "l"(a), "l"(b));
}

// ---------------- scratch (device globals; no allocation allowed) ----------
__device__ float g_u  [BATCH*CF*HW];        // upsampled features
__device__ float g_h1 [BATCH*NB*KT*HW];     // conv1 out
__device__ float g_h2 [BATCH*NB*KT*HW];     // conv2 out
__device__ float g_h3 [BATCH*NB*KT*HW];     // conv3 out (the 4 kernel maps)
__device__ float g_w1t[NB*CF*9*OCP];        // transposed/padded weights
__device__ float g_w2t[NB*KT*9*OCP];
__device__ float g_w3t[NB*KT*9*OCP];

// ---------------- 2x bilinear upsample, align_corners=True ----------------
__global__ void upsample_k(const float* __restrict__ x)
{
    int idx = blockIdx.x * blockDim.x + threadIdx.x;
    const int total = BATCH*CF*HW;
    if (idx >= total) return;
    int xo = idx % W;
    int t  = idx / W;
    int yo = t % H;
    t      = t / H;      // t = b*CF + c

    const float s = (float)(HH - 1) / (float)(H - 1);   // 127/255
    float fy = (float)yo * s;
    int   ly = (int)floorf(fy);
    float wy = fy - (float)ly;
    int   hy = min(ly + 1, HH - 1);
    float fx = (float)xo * s;
    int   lx = (int)floorf(fx);
    float wx = fx - (float)lx;
    int   hx = min(lx + 1, WHALF - 1);

    const float* xp = x + (size_t)t * HH * WHALF;
    float a = xp[ly*WHALF + lx];
    float b = xp[hy*WHALF + lx];
    float c = xp[ly*WHALF + hx];
    float d = xp[hy*WHALF + hx];
    float col0 = a*(1.f-wy) + b*wy;     // H-lerp first (matches reference order)
    float col1 = c*(1.f-wy) + d*wy;
    g_u[idx] = col0*(1.f-wx) + col1*wx; // then W-lerp
}

// ------------- weight transpose:  [g*KT+oc][ic][3][3] -> [g][ic][tap][OCP] --
__global__ void wprep_k(const float* __restrict__ w, float* __restrict__ wt, int cin)
{
    int idx = blockIdx.x * blockDim.x + threadIdx.x;
    int total = NB * cin * 9 * OCP;
    if (idx >= total) return;
    int oc  = idx % OCP;
    int t   = idx / OCP;
    int tap = t % 9;
    t       = t / 9;
    int ic  = t % cin;
    int g   = t / cin;
    float v = 0.f;
    if (oc < KT) v = w[(((size_t)(g*KT + oc) * cin + ic) * 9) + tap];
    wt[idx] = v;
}

// ---------------- conv3x3 + bias + relu (packed f32x2 math) ---------------
// CIN = input channels per group. GROUPED=false: all groups read same CIN
// input channels (conv1). GROUPED=true: group g reads channels [g*CIN, ...).
// grid: (W/16, H/16, BATCH*NB); block 256 = 16x16 pixels; each thread owns
// all OCP output-channel accumulators (as 26 packed f32x2) for its pixel.
template<int CIN, bool GROUPED>
__global__ __launch_bounds__(256, 2)
void conv3x3_k(const float* __restrict__ in, const float* __restrict__ wt,
               const float* __restrict__ bias, float* __restrict__ out)
{
    constexpr int ICB = 8;
    __shared__ float s_in[ICB][18][18];
    __shared__ __align__(16) float s_w [ICB * 9 * OCP];

    const int tx = threadIdx.x & 15;
    const int ty = threadIdx.x >> 4;
    const int x0 = blockIdx.x * 16;
    const int y0 = blockIdx.y * 16;
    const int bz = blockIdx.z;
    const int g  = bz % NB;
    const int b  = bz / NB;

    const float* inb = GROUPED
        ? in + ((size_t)b * NB * CIN + (size_t)g * CIN) * HW
        : in + (size_t)b * CIN * HW;
    const float* wg = wt + (size_t)g * CIN * 9 * OCP;

    u64 acc[OCP/2];
#pragma unroll
    for (int o = 0; o < OCP/2; o++) {
        float blo = bias[g*KT + 2*o];
        float bhi = (2*o + 1 < KT) ? bias[g*KT + 2*o + 1] : 0.f;
        acc[o] = pack2(blo, bhi);
    }

    for (int ic0 = 0; ic0 < CIN; ic0 += ICB) {
        const int icb = (CIN - ic0 < ICB) ? (CIN - ic0) : ICB;
        __syncthreads();
        // stage input tile (with 1-px halo, zero padded)
        for (int li = threadIdx.x; li < icb*18*18; li += 256) {
            int p  = li % (18*18);
            int ic = li / (18*18);
            int iy = p / 18, ix = p % 18;
            int gy = y0 + iy - 1, gx = x0 + ix - 1;
            float v = 0.f;
            if (gy >= 0 && gy < H && gx >= 0 && gx < W)
                v = inb[(size_t)(ic0+ic)*HW + (size_t)gy*W + gx];
            s_in[ic][iy][ix] = v;
        }
        // stage weight chunk (contiguous, float4)
        {
            const float4* ws = (const float4*)(wg + (size_t)ic0 * 9 * OCP);
            float4* sd = (float4*)s_w;
            const int nf4 = icb * 9 * (OCP/4);
            for (int li = threadIdx.x; li < nf4; li += 256) sd[li] = ws[li];
        }
        __syncthreads();

        for (int ic = 0; ic < icb; ic++) {
#pragma unroll
            for (int ky = 0; ky < 3; ky++) {
#pragma unroll
                for (int kx = 0; kx < 3; kx++) {
                    float rin = s_in[ic][ty+ky][tx+kx];
                    u64 rin2 = pack2(rin, rin);
                    const ulonglong2* wrow =
                        (const ulonglong2*)&s_w[(ic*9 + ky*3 + kx) * OCP];
#pragma unroll
                    for (int q = 0; q < OCP/4; q++) {
                        ulonglong2 wv = wrow[q];   // LDS.128, uniform broadcast
                        fma2(acc[2*q+0], rin2, wv.x);
                        fma2(acc[2*q+1], rin2, wv.y);
                    }
                }
            }
        }
    }

    size_t ob = ((size_t)b * NB * KT + (size_t)g * KT) * HW
              + (size_t)(y0 + ty) * W + (x0 + tx);
#pragma unroll
    for (int o = 0; o < OCP/2; o++) {
        float lo, hi;
        unpack2(acc[o], lo, hi);
        out[ob + (size_t)(2*o) * HW] = fmaxf(lo, 0.f);
        if (2*o + 1 < KT)
            out[ob + (size_t)(2*o+1) * HW] = fmaxf(hi, 0.f);
    }
}

// ---------------- separable 51-tap conv + sum of the two frames -----------
// out[b,c,y,x] = sum_j kh[j] * (sum_i kv[i] * img[b,c,y+i,x+j])   (per frame)
// grid: (16,16,BATCH); block 256 = 16x16. Image tile stored as
// neighbor-pairs: s_dup[row][k] = (img[k], img[k+1]) so each thread's
// 2-tap group (j, j+1) is one aligned LDS.64 + one packed FMA.
__global__ __launch_bounds__(256, 2)
void sepconv_k(const float* __restrict__ i1, const float* __restrict__ i2,
               float* __restrict__ out)
{
    __shared__ u64 s_dup[66 * 80];   // row stride 80 ull: halves of a warp on
                                     // separate 128B phases -> conflict-free
    const int tx = threadIdx.x & 15;
    const int ty = threadIdx.x >> 4;
    const int x0 = blockIdx.x * 16;
    const int y0 = blockIdx.y * 16;
    const int b  = blockIdx.z;
    const int y  = y0 + ty, x = x0 + tx;

    const float* kbase = g_h3 + (size_t)b * NB * KT * HW + (size_t)y * W + x;
    float acc[3] = {0.f, 0.f, 0.f};

    for (int im = 0; im < 2; im++) {
        const float* img = im ? i2 : i1;
        const float* kv = kbase + (size_t)(im*2    ) * KT * HW;  // branch 0 / 2
        const float* kh = kbase + (size_t)(im*2 + 1) * KT * HW;  // branch 1 / 3

        for (int c = 0; c < 3; c++) {
            __syncthreads();
            const float* ib = img + ((size_t)b * 3 + c) * IMGW * IMGW;
            for (int li = threadIdx.x; li < 66*66; li += 256) {
                int iy = li / 66, ix = li % 66;
                const float* p = ib + (size_t)(y0 + iy) * IMGW + (x0 + ix);
                float a0 = p[0];
                float a1 = (ix < 65) ? p[1] : 0.f;
                s_dup[iy*80 + ix] = pack2(a0, a1);
            }
            __syncthreads();

            u64 v2[25];                 // taps j = 0..49 in pairs
            float vlast = 0.f;          // tap j = 50
#pragma unroll
            for (int q = 0; q < 25; q++) v2[q] = 0;

            for (int i = 0; i < KT; i++) {
                float kvi = kv[(size_t)i * HW];
                u64 kv2 = pack2(kvi, kvi);
                const u64* srow = &s_dup[(ty + i) * 80 + tx];
#pragma unroll
                for (int q = 0; q < 25; q++)
                    fma2(v2[q], kv2, srow[2*q]);
                // tap 50: lo half of pair at tx+50
                float s50 = ((const float*)&srow[50])[0];
                vlast = fmaf(kvi, s50, vlast);
            }
            float o = 0.f;
#pragma unroll
            for (int q = 0; q < 25; q++) {
                float vlo, vhi;
                unpack2(v2[q], vlo, vhi);
                o = fmaf(kh[(size_t)(2*q  ) * HW], vlo, o);
                o = fmaf(kh[(size_t)(2*q+1) * HW], vhi, o);
            }
            o = fmaf(kh[(size_t)50 * HW], vlast, o);
            acc[c] += o;
        }
    }

    size_t ob = (size_t)b * 3 * HW + (size_t)y * W + x;
#pragma unroll
    for (int c = 0; c < 3; c++)
        out[ob + (size_t)c * HW] = acc[c];
}

// ---------------- launch ---------------------------------------------------
extern "C" void kernel_launch(void* const* d_in, const int* in_sizes, int n_in,
                              void* d_out, int out_size)
{
    const float* x  = (const float*)d_in[0];
    const float* i1 = (const float*)d_in[1];
    const float* i2 = (const float*)d_in[2];
    const float* W1 = (const float*)d_in[3];
    const float* B1 = (const float*)d_in[4];
    const float* W2 = (const float*)d_in[5];
    const float* B2 = (const float*)d_in[6];
    const float* W3 = (const float*)d_in[7];
    const float* B3 = (const float*)d_in[8];
    float* out = (float*)d_out;

    float *u, *h1, *h2, *h3, *w1t, *w2t, *w3t;
    cudaGetSymbolAddress((void**)&u,   g_u);
    cudaGetSymbolAddress((void**)&h1,  g_h1);
    cudaGetSymbolAddress((void**)&h2,  g_h2);
    cudaGetSymbolAddress((void**)&h3,  g_h3);
    cudaGetSymbolAddress((void**)&w1t, g_w1t);
    cudaGetSymbolAddress((void**)&w2t, g_w2t);
    cudaGetSymbolAddress((void**)&w3t, g_w3t);

    // weight transpose (tiny)
    {
        int n1 = NB*CF*9*OCP, n2 = NB*KT*9*OCP;
        wprep_k<<<(n1 + 255)/256, 256>>>(W1, w1t, CF);
        wprep_k<<<(n2 + 255)/256, 256>>>(W2, w2t, KT);
        wprep_k<<<(n2 + 255)/256, 256>>>(W3, w3t, KT);
    }

    // upsample
    {
        int n = BATCH*CF*HW;
        upsample_k<<<(n + 255)/256, 256>>>(x);
    }

    dim3 cgrid(W/16, H/16, BATCH*NB);
    dim3 cblk(256);
    conv3x3_k<CF, false><<<cgrid, cblk>>>(u,  w1t, B1, h1);
    conv3x3_k<KT, true ><<<cgrid, cblk>>>(h1, w2t, B2, h2);
    conv3x3_k<KT, true ><<<cgrid, cblk>>>(h2, w3t, B3, h3);

    dim3 sgrid(W/16, H/16, BATCH);
    sepconv_k<<<sgrid, cblk>>>(i1, i2, out);

    (void)in_sizes; (void)n_in; (void)out_size;
}

// round 5
// speedup vs baseline: 1.5126x; 1.4770x over previous
#include <cuda_runtime.h>
#include <mma.h>
#include <math.h>

using namespace nvcuda;

// ---------------- problem constants ----------------
#define BATCH 4
#define CF    64
#define HH    128
#define WHALF 128
#define H     256
#define W     256
#define KT    51
#define OC64  64        // padded output channels for wmma (4 x n16)
#define NB    4
#define PADI  25
#define IMGW  306
#define HW    (H*W)
#define CFP   64        // padded cin conv1
#define KTP   56        // padded cin conv2/3 (51 -> 56, mult of 8)

typedef unsigned long long u64;

// ---------------- packed f32x2 helpers -------------------------------------
__device__ __forceinline__ u64 pack2(float lo, float hi) {
    u64 r;
    asm("mov.b64 %0, {%1, %2};" : "=l"(r) : "f"(lo), "f"(hi));
    return r;
}
__device__ __forceinline__ void unpack2(u64 v, float& lo, float& hi) {
    asm("mov.b64 {%0, %1}, %2;" : "=f"(lo), "=f"(hi) : "l"(v));
}
__device__ __forceinline__ void fma2(u64& acc, u64 a, u64 b) {
    asm("fma.rn.f32x2 %0, %1, %2, %0;" : "+l"(acc) : "l"(a), "l"(b));
}

// ---------------- scratch --------------------------------------------------
__device__ float g_u  [BATCH*CF*HW];
__device__ float g_h1 [BATCH*NB*KT*HW];
__device__ float g_h2 [BATCH*NB*KT*HW];
__device__ float g_h3 [BATCH*NB*KT*HW];
__device__ float g_w1t[NB*9*CFP*OC64];
__device__ float g_w2t[NB*9*KTP*OC64];
__device__ float g_w3t[NB*9*KTP*OC64];

// ---------------- 2x bilinear upsample, align_corners=True ----------------
__global__ void upsample_k(const float* __restrict__ x)
{
    int idx = blockIdx.x * blockDim.x + threadIdx.x;
    const int total = BATCH*CF*HW;
    if (idx >= total) return;
    int xo = idx % W;
    int t  = idx / W;
    int yo = t % H;
    t      = t / H;

    const float s = (float)(HH - 1) / (float)(H - 1);
    float fy = (float)yo * s;
    int   ly = (int)floorf(fy);
    float wy = fy - (float)ly;
    int   hy = min(ly + 1, HH - 1);
    float fx = (float)xo * s;
    int   lx = (int)floorf(fx);
    float wx = fx - (float)lx;
    int   hx = min(lx + 1, WHALF - 1);

    const float* xp = x + (size_t)t * HH * WHALF;
    float a = xp[ly*WHALF + lx];
    float b = xp[hy*WHALF + lx];
    float c = xp[ly*WHALF + hx];
    float d = xp[hy*WHALF + hx];
    float col0 = a*(1.f-wy) + b*wy;
    float col1 = c*(1.f-wy) + d*wy;
    g_u[idx] = col0*(1.f-wx) + col1*wx;
}

// ------ weight transpose: [g*KT+oc][ic][3][3] -> [g][tap][icPad][OC64] -----
__global__ void wprep2_k(const float* __restrict__ w, float* __restrict__ wt,
                         int cin, int cinp)
{
    int idx = blockIdx.x * blockDim.x + threadIdx.x;
    int total = NB * 9 * cinp * OC64;
    if (idx >= total) return;
    int oc  = idx & 63;
    int t   = idx >> 6;
    int ic  = t % cinp;
    t       = t / cinp;
    int tap = t % 9;
    int g   = t / 9;
    float v = 0.f;
    if (oc < KT && ic < cin)
        v = w[(((size_t)(g*KT + oc) * cin + ic) * 9) + tap];
    wt[idx] = v;
}

// ---------------- conv3x3 + bias + relu via wmma TF32 ----------------------
// Implicit GEMM: A[m=16 px][k=8 ic] (NHWC smem tile, ld=8), B[k=8][n=64 oc]
// (ld=64). Block: 16x16 pixels, 64 oc, one (b,g). 8 warps x (2 M x 4 N)
// m16n16k8 accumulators. K-loop: ic chunks of 8, 9 taps each.
template<int CIN, int CINP, bool GROUPED>
__global__ __launch_bounds__(256, 2)
void conv3x3_wmma_k(const float* __restrict__ in, const float* __restrict__ wt,
                    const float* __restrict__ bias, float* __restrict__ out)
{
    __shared__ float s_in[18*18*8];     // NHWC input chunk (10368 B)
    __shared__ float s_w [9*8*OC64];    // weight chunk     (18432 B)
    __shared__ float s_st[8*16*20];     // per-warp epilogue staging (10240 B)

    const int tid  = threadIdx.x;
    const int warp = tid >> 5;
    const int lane = tid & 31;
    const int x0 = blockIdx.x * 16;
    const int y0 = blockIdx.y * 16;
    const int g  = blockIdx.z % NB;
    const int b  = blockIdx.z / NB;

    const float* inb = GROUPED
        ? in + ((size_t)b * NB * CIN + (size_t)g * CIN) * HW
        : in + (size_t)b * CIN * HW;
    const float* wg = wt + (size_t)g * 9 * CINP * OC64;

    wmma::fragment<wmma::accumulator, 16, 16, 8, float> c[2][4];
#pragma unroll
    for (int mt = 0; mt < 2; mt++)
#pragma unroll
        for (int nt = 0; nt < 4; nt++)
            wmma::fill_fragment(c[mt][nt], 0.f);

    for (int ic0 = 0; ic0 < CINP; ic0 += 8) {
        __syncthreads();
        // stage input 18x18 x 8ch as NHWC (zero pad halo + ic tail)
        for (int li = tid; li < 324*8; li += 256) {
            int ic = li / 324;
            int p  = li % 324;
            int iy = p / 18, ix = p % 18;
            int gy = y0 + iy - 1, gx = x0 + ix - 1;
            int icg = ic0 + ic;
            float v = 0.f;
            if (icg < CIN && gy >= 0 && gy < H && gx >= 0 && gx < W)
                v = inb[(size_t)icg * HW + (size_t)gy * W + gx];
            s_in[p*8 + ic] = v;
        }
        // stage weights: 9 taps x 8 ic x 64 oc (float4)
        {
            const float4* src = (const float4*)wg;
            float4* dst = (float4*)s_w;
            for (int li = tid; li < 9*8*16; li += 256) {
                int oc4 = li & 15;
                int t2  = li >> 4;
                int ic  = t2 & 7;
                int tap = t2 >> 3;
                dst[(tap*8 + ic)*16 + oc4] =
                    src[((size_t)tap*CINP + ic0 + ic)*16 + oc4];
            }
        }
        __syncthreads();

        const int py0 = warp * 2;
#pragma unroll
        for (int tap = 0; tap < 9; tap++) {
            const int ky = tap / 3, kx = tap % 3;
            wmma::fragment<wmma::matrix_b, 16, 16, 8,
                           wmma::precision::tf32, wmma::row_major> bf[4];
#pragma unroll
            for (int nt = 0; nt < 4; nt++) {
                wmma::load_matrix_sync(bf[nt], s_w + (tap*8)*OC64 + nt*16, OC64);
#pragma unroll
                for (int e = 0; e < bf[nt].num_elements; e++)
                    bf[nt].x[e] = wmma::__float_to_tf32(bf[nt].x[e]);
            }
#pragma unroll
            for (int mt = 0; mt < 2; mt++) {
                wmma::fragment<wmma::matrix_a, 16, 16, 8,
                               wmma::precision::tf32, wmma::row_major> af;
                wmma::load_matrix_sync(af,
                    s_in + ((py0 + mt + ky)*18 + kx)*8, 8);
#pragma unroll
                for (int e = 0; e < af.num_elements; e++)
                    af.x[e] = wmma::__float_to_tf32(af.x[e]);
#pragma unroll
                for (int nt = 0; nt < 4; nt++)
                    wmma::mma_sync(c[mt][nt], af, bf[nt], c[mt][nt]);
            }
        }
    }

    // epilogue: per-warp staging -> bias + relu -> global NCHW
    float* st = s_st + warp * 16 * 20;
    const size_t obase = ((size_t)b * NB + g) * KT * HW;
#pragma unroll
    for (int mt = 0; mt < 2; mt++) {
        const int py = warp*2 + mt;
#pragma unroll
        for (int nt = 0; nt < 4; nt++) {
            wmma::store_matrix_sync(st, c[mt][nt], 20, wmma::mem_row_major);
            __syncwarp();
#pragma unroll
            for (int i = 0; i < 8; i++) {
                int idx = lane + 32*i;
                int m = idx & 15;       // x offset
                int n = idx >> 4;       // oc within n-tile
                int oc = nt*16 + n;
                if (oc < KT) {
                    float v = st[m*20 + n] + bias[g*KT + oc];
                    out[obase + (size_t)oc * HW
                        + (size_t)(y0 + py) * W + (x0 + m)] = fmaxf(v, 0.f);
                }
            }
            __syncwarp();
        }
    }
}

// ---------------- separable 51-tap conv + sum of the two frames -----------
__global__ __launch_bounds__(256, 2)
void sepconv_k(const float* __restrict__ i1, const float* __restrict__ i2,
               float* __restrict__ out)
{
    __shared__ u64 s_dup[66 * 80];
    const int tx = threadIdx.x & 15;
    const int ty = threadIdx.x >> 4;
    const int x0 = blockIdx.x * 16;
    const int y0 = blockIdx.y * 16;
    const int b  = blockIdx.z;
    const int y  = y0 + ty, x = x0 + tx;

    const float* kbase = g_h3 + (size_t)b * NB * KT * HW + (size_t)y * W + x;
    float acc[3] = {0.f, 0.f, 0.f};

    for (int im = 0; im < 2; im++) {
        const float* img = im ? i2 : i1;
        const float* kv = kbase + (size_t)(im*2    ) * KT * HW;
        const float* kh = kbase + (size_t)(im*2 + 1) * KT * HW;

        for (int c = 0; c < 3; c++) {
            __syncthreads();
            const float* ib = img + ((size_t)b * 3 + c) * IMGW * IMGW;
            for (int li = threadIdx.x; li < 66*66; li += 256) {
                int iy = li / 66, ix = li % 66;
                const float* p = ib + (size_t)(y0 + iy) * IMGW + (x0 + ix);
                float a0 = p[0];
                float a1 = (ix < 65) ? p[1] : 0.f;
                s_dup[iy*80 + ix] = pack2(a0, a1);
            }
            __syncthreads();

            u64 v2[25];
            float vlast = 0.f;
#pragma unroll
            for (int q = 0; q < 25; q++) v2[q] = 0;

            for (int i = 0; i < KT; i++) {
                float kvi = kv[(size_t)i * HW];
                u64 kv2 = pack2(kvi, kvi);
                const u64* srow = &s_dup[(ty + i) * 80 + tx];
#pragma unroll
                for (int q = 0; q < 25; q++)
                    fma2(v2[q], kv2, srow[2*q]);
                float s50 = ((const float*)&srow[50])[0];
                vlast = fmaf(kvi, s50, vlast);
            }
            float o = 0.f;
#pragma unroll
            for (int q = 0; q < 25; q++) {
                float vlo, vhi;
                unpack2(v2[q], vlo, vhi);
                o = fmaf(kh[(size_t)(2*q  ) * HW], vlo, o);
                o = fmaf(kh[(size_t)(2*q+1) * HW], vhi, o);
            }
            o = fmaf(kh[(size_t)50 * HW], vlast, o);
            acc[c] += o;
        }
    }

    size_t ob = (size_t)b * 3 * HW + (size_t)y * W + x;
#pragma unroll
    for (int c = 0; c < 3; c++)
        out[ob + (size_t)c * HW] = acc[c];
}

// ---------------- launch ---------------------------------------------------
extern "C" void kernel_launch(void* const* d_in, const int* in_sizes, int n_in,
                              void* d_out, int out_size)
{
    const float* x  = (const float*)d_in[0];
    const float* i1 = (const float*)d_in[1];
    const float* i2 = (const float*)d_in[2];
    const float* W1 = (const float*)d_in[3];
    const float* B1 = (const float*)d_in[4];
    const float* W2 = (const float*)d_in[5];
    const float* B2 = (const float*)d_in[6];
    const float* W3 = (const float*)d_in[7];
    const float* B3 = (const float*)d_in[8];
    float* out = (float*)d_out;

    float *u, *h1, *h2, *h3, *w1t, *w2t, *w3t;
    cudaGetSymbolAddress((void**)&u,   g_u);
    cudaGetSymbolAddress((void**)&h1,  g_h1);
    cudaGetSymbolAddress((void**)&h2,  g_h2);
    cudaGetSymbolAddress((void**)&h3,  g_h3);
    cudaGetSymbolAddress((void**)&w1t, g_w1t);
    cudaGetSymbolAddress((void**)&w2t, g_w2t);
    cudaGetSymbolAddress((void**)&w3t, g_w3t);

    {
        int n1 = NB*9*CFP*OC64, n2 = NB*9*KTP*OC64;
        wprep2_k<<<(n1 + 255)/256, 256>>>(W1, w1t, CF, CFP);
        wprep2_k<<<(n2 + 255)/256, 256>>>(W2, w2t, KT, KTP);
        wprep2_k<<<(n2 + 255)/256, 256>>>(W3, w3t, KT, KTP);
    }
    {
        int n = BATCH*CF*HW;
        upsample_k<<<(n + 255)/256, 256>>>(x);
    }

    dim3 cgrid(W/16, H/16, BATCH*NB);
    dim3 cblk(256);
    conv3x3_wmma_k<CF, CFP, false><<<cgrid, cblk>>>(u,  w1t, B1, h1);
    conv3x3_wmma_k<KT, KTP, true ><<<cgrid, cblk>>>(h1, w2t, B2, h2);
    conv3x3_wmma_k<KT, KTP, true ><<<cgrid, cblk>>>(h2, w3t, B3, h3);

    dim3 sgrid(W/16, H/16, BATCH);
    sepconv_k<<<sgrid, cblk>>>(i1, i2, out);

    (void)in_sizes; (void)n_in; (void)out_size;
}

// round 7
// speedup vs baseline: 1.6224x; 1.0726x over previous
#include <cuda_runtime.h>
#include <mma.h>
#include <math.h>

using namespace nvcuda;

// ---------------- problem constants ----------------
#define BATCH 4
#define CF    64
#define HH    128
#define WHALF 128
#define H     256
#define W     256
#define KT    51
#define OC64  64
#define NB    4
#define PADI  25
#define IMGW  306
#define HW    (H*W)
#define CFP   64        // padded cin conv1
#define KTP   56        // padded cin conv2/3

typedef unsigned long long u64;

__device__ __forceinline__ float to_tf32(float v) {
    return wmma::__float_to_tf32(v);
}

// ---------------- packed f32x2 helpers (sepconv) ---------------------------
__device__ __forceinline__ u64 pack2(float lo, float hi) {
    u64 r;
    asm("mov.b64 %0, {%1, %2};" : "=l"(r) : "f"(lo), "f"(hi));
    return r;
}
__device__ __forceinline__ void unpack2(u64 v, float& lo, float& hi) {
    asm("mov.b64 {%0, %1}, %2;" : "=f"(lo), "=f"(hi) : "l"(v));
}
__device__ __forceinline__ void fma2(u64& acc, u64 a, u64 b) {
    asm("fma.rn.f32x2 %0, %1, %2, %0;" : "+l"(acc) : "l"(a), "l"(b));
}

// ---------------- scratch --------------------------------------------------
__device__ float g_u  [BATCH*HW*OC64];        // NHWC, tf32-rounded
__device__ float g_h1 [BATCH*NB*HW*OC64];     // NHWC, tf32-rounded
__device__ float g_h2 [BATCH*NB*HW*OC64];     // NHWC, tf32-rounded
__device__ float g_h3 [BATCH*NB*KT*HW];       // NCHW fp32 (sepconv input)
__device__ float g_w1t[NB*9*CFP*OC64];        // [g][tap][icPad][64], tf32
__device__ float g_w2t[NB*9*KTP*OC64];
__device__ float g_w3t[NB*9*KTP*OC64];

// ---------------- 2x bilinear upsample -> NHWC + tf32 round ---------------
// block = 256 threads handles 64 consecutive x at one (b, y): smem transpose
// so both the NCHW reads and the NHWC writes are coalesced.
__global__ void upsample_k(const float* __restrict__ x)
{
    __shared__ float s[64 * 65];
    const int p0  = blockIdx.x * 64;          // linear px over BATCH*HW
    const int b   = p0 / HW;
    const int rem = p0 - b * HW;
    const int y   = rem / W;
    const int xb  = rem % W;

    const float sc = (float)(HH - 1) / (float)(H - 1);
    const float fy = (float)y * sc;
    const int   ly = (int)floorf(fy);
    const float wy = fy - (float)ly;
    const int   hy = min(ly + 1, HH - 1);

    const int tid = threadIdx.x;
    const int c   = tid >> 2;
    const int sub = tid & 3;
    const float* xc = x + ((size_t)b * CF + c) * HH * WHALF;

#pragma unroll 4
    for (int i = 0; i < 16; i++) {
        int px = sub * 16 + i;
        int gx = xb + px;
        float fx = (float)gx * sc;
        int   lx = (int)floorf(fx);
        float wx = fx - (float)lx;
        int   hx = min(lx + 1, WHALF - 1);
        float a  = xc[ly*WHALF + lx];
        float bb = xc[hy*WHALF + lx];
        float cc = xc[ly*WHALF + hx];
        float dd = xc[hy*WHALF + hx];
        float v = (a*(1.f-wy) + bb*wy)*(1.f-wx) + (cc*(1.f-wy) + dd*wy)*wx;
        s[px*65 + c] = to_tf32(v);
    }
    __syncthreads();
    float* outb = g_u + (size_t)p0 * OC64;
#pragma unroll 4
    for (int i = 0; i < 16; i++) {
        int idx = tid + 256*i;
        int cc2 = idx & 63, px = idx >> 6;
        outb[px*OC64 + cc2] = s[px*65 + cc2];
    }
}

// ------ weight transpose + tf32 round: -> [g][tap][icPad][OC64] ------------
__global__ void wprep2_k(const float* __restrict__ w, float* __restrict__ wt,
                         int cin, int cinp)
{
    int idx = blockIdx.x * blockDim.x + threadIdx.x;
    int total = NB * 9 * cinp * OC64;
    if (idx >= total) return;
    int oc  = idx & 63;
    int t   = idx >> 6;
    int ic  = t % cinp;
    t       = t / cinp;
    int tap = t % 9;
    int g   = t / 9;
    float v = 0.f;
    if (oc < KT && ic < cin)
        v = w[(((size_t)(g*KT + oc) * cin + ic) * 9) + tap];
    wt[idx] = to_tf32(v);
}

// ---------------- conv3x3 + bias + relu via wmma TF32 ----------------------
// NHWC input (stride 64/px), pre-rounded tf32 -> no per-fragment cvt.
// Block: 16x16 px, 64 oc, one (b,g). 8 warps x (2M x 4N) m16n16k8 frags.
// NCHW_OUT=false: NHWC tf32-rounded output (h1,h2). true: NCHW fp32 (h3).
template<int CINP, bool GROUPED, bool NCHW_OUT>
__global__ __launch_bounds__(256, 2)
void conv3x3_wmma_k(const float* __restrict__ in, const float* __restrict__ wt,
                    const float* __restrict__ bias, float* __restrict__ out)
{
    __shared__ float s_pool[8*16*72];   // epilogue staging; aliases s_in+s_w
    __shared__ float s_bias[64];
    float* s_in = s_pool;               // 18*18*8 = 2592 floats
    float* s_w  = s_pool + 2592;        // 9*8*64  = 4608 floats (end 7200)

    const int tid  = threadIdx.x;
    const int warp = tid >> 5;
    const int lane = tid & 31;
    const int x0 = blockIdx.x * 16;
    const int y0 = blockIdx.y * 16;
    const int g  = blockIdx.z % NB;
    const int b  = blockIdx.z / NB;

    const float* inb = GROUPED
        ? in + (size_t)(b*NB + g) * HW * OC64
        : in + (size_t)b * HW * OC64;
    const float* wg = wt + (size_t)g * 9 * CINP * OC64;

    if (tid < 64) s_bias[tid] = (tid < KT) ? bias[g*KT + tid] : 0.f;

    wmma::fragment<wmma::accumulator, 16, 16, 8, float> c[2][4];
#pragma unroll
    for (int mt = 0; mt < 2; mt++)
#pragma unroll
        for (int nt = 0; nt < 4; nt++)
            wmma::fill_fragment(c[mt][nt], 0.f);

    for (int ic0 = 0; ic0 < CINP; ic0 += 8) {
        __syncthreads();
        // stage input: 18x18 px, 8 ch -> 2 float4 per px (NHWC source)
        for (int li = tid; li < 324*2; li += 256) {
            int px = li >> 1, q = li & 1;
            int iy = px / 18, ix = px % 18;
            int gy = y0 + iy - 1, gx = x0 + ix - 1;
            float4 v = make_float4(0.f, 0.f, 0.f, 0.f);
            if ((unsigned)gy < H && (unsigned)gx < W)
                v = *(const float4*)(inb + ((size_t)gy*W + gx)*OC64 + ic0 + q*4);
            *(float4*)(s_in + px*8 + q*4) = v;
        }
        // stage weights: 9 taps x 8 ic x 64 oc
        for (int li = tid; li < 9*8*16; li += 256) {
            int oc4 = li & 15;
            int t2  = li >> 4;
            int ic  = t2 & 7;
            int tap = t2 >> 3;
            ((float4*)s_w)[(tap*8 + ic)*16 + oc4] =
                ((const float4*)wg)[((size_t)tap*CINP + ic0 + ic)*16 + oc4];
        }
        __syncthreads();

        const int py0 = warp * 2;
#pragma unroll
        for (int tap = 0; tap < 9; tap++) {
            const int ky = tap / 3, kx = tap % 3;
            wmma::fragment<wmma::matrix_b, 16, 16, 8,
                           wmma::precision::tf32, wmma::row_major> bf[4];
#pragma unroll
            for (int nt = 0; nt < 4; nt++)
                wmma::load_matrix_sync(bf[nt], s_w + (tap*8)*OC64 + nt*16, OC64);
#pragma unroll
            for (int mt = 0; mt < 2; mt++) {
                wmma::fragment<wmma::matrix_a, 16, 16, 8,
                               wmma::precision::tf32, wmma::row_major> af;
                wmma::load_matrix_sync(af, s_in + ((py0 + mt + ky)*18 + kx)*8, 8);
#pragma unroll
                for (int nt = 0; nt < 4; nt++)
                    wmma::mma_sync(c[mt][nt], af, bf[nt], c[mt][nt]);
            }
        }
    }

    __syncthreads();   // s_in/s_w dead; pool becomes epilogue staging
    float* st = s_pool + warp * 16 * 72;

    if (!NCHW_OUT) {
        // NHWC tf32-rounded output (h1 / h2)
        const size_t obase = (size_t)(b*NB + g) * HW * OC64;
#pragma unroll
        for (int mt = 0; mt < 2; mt++) {
            const int py = warp*2 + mt;
#pragma unroll
            for (int nt = 0; nt < 4; nt++)
                wmma::store_matrix_sync(st + nt*16, c[mt][nt], 72,
                                        wmma::mem_row_major);
            __syncwarp();
            const int px   = lane >> 1;
            const int cofs = (lane & 1) * 32;
            const float* row = st + px*72 + cofs;
            float* orow = out + obase + ((size_t)(y0+py)*W + x0 + px)*OC64 + cofs;
#pragma unroll
            for (int j = 0; j < 8; j++) {
                int oc = cofs + j*4;
                float4 v;
                v.x = to_tf32(fmaxf(row[j*4+0] + s_bias[oc+0], 0.f));
                v.y = to_tf32(fmaxf(row[j*4+1] + s_bias[oc+1], 0.f));
                v.z = to_tf32(fmaxf(row[j*4+2] + s_bias[oc+2], 0.f));
                v.w = to_tf32(fmaxf(row[j*4+3] + s_bias[oc+3], 0.f));
                *(float4*)(orow + j*4) = v;
            }
            __syncwarp();
        }
    } else {
        // NCHW fp32 output (h3, feeds sepconv)
        const size_t obase = (size_t)(b*NB + g) * KT * HW;
#pragma unroll
        for (int mt = 0; mt < 2; mt++) {
            const int py = warp*2 + mt;
#pragma unroll
            for (int nt = 0; nt < 4; nt++) {
                wmma::store_matrix_sync(st, c[mt][nt], 72, wmma::mem_row_major);
                __syncwarp();
#pragma unroll
                for (int i = 0; i < 8; i++) {
                    int idx = lane + 32*i;
                    int m = idx & 15;
                    int n = idx >> 4;
                    int oc = nt*16 + n;
                    if (oc < KT)
                        out[obase + (size_t)oc*HW + (size_t)(y0+py)*W + x0 + m]
                            = fmaxf(st[m*72 + n] + s_bias[oc], 0.f);
                }
                __syncwarp();
            }
        }
    }
}

// ---------------- separable 51-tap conv + sum of the two frames -----------
__global__ __launch_bounds__(256, 2)
void sepconv_k(const float* __restrict__ i1, const float* __restrict__ i2,
               float* __restrict__ out)
{
    __shared__ u64 s_dup[66 * 80];
    const int tx = threadIdx.x & 15;
    const int ty = threadIdx.x >> 4;
    const int x0 = blockIdx.x * 16;
    const int y0 = blockIdx.y * 16;
    const int b  = blockIdx.z;
    const int y  = y0 + ty, x = x0 + tx;

    const float* kbase = g_h3 + (size_t)b * NB * KT * HW + (size_t)y * W + x;
    float acc[3] = {0.f, 0.f, 0.f};

    for (int im = 0; im < 2; im++) {
        const float* img = im ? i2 : i1;
        const float* kv = kbase + (size_t)(im*2    ) * KT * HW;
        const float* kh = kbase + (size_t)(im*2 + 1) * KT * HW;

        for (int c = 0; c < 3; c++) {
            __syncthreads();
            const float* ib = img + ((size_t)b * 3 + c) * IMGW * IMGW;
            for (int li = threadIdx.x; li < 66*66; li += 256) {
                int iy = li / 66, ix = li % 66;
                const float* p = ib + (size_t)(y0 + iy) * IMGW + (x0 + ix);
                float a0 = p[0];
                float a1 = (ix < 65) ? p[1] : 0.f;
                s_dup[iy*80 + ix] = pack2(a0, a1);
            }
            __syncthreads();

            u64 v2[25];
            float vlast = 0.f;
#pragma unroll
            for (int q = 0; q < 25; q++) v2[q] = 0;

            for (int i = 0; i < KT; i++) {
                float kvi = kv[(size_t)i * HW];
                u64 kv2 = pack2(kvi, kvi);
                const u64* srow = &s_dup[(ty + i) * 80 + tx];
#pragma unroll
                for (int q = 0; q < 25; q++)
                    fma2(v2[q], kv2, srow[2*q]);
                float s50 = ((const float*)&srow[50])[0];
                vlast = fmaf(kvi, s50, vlast);
            }
            float o = 0.f;
#pragma unroll
            for (int q = 0; q < 25; q++) {
                float vlo, vhi;
                unpack2(v2[q], vlo, vhi);
                o = fmaf(kh[(size_t)(2*q  ) * HW], vlo, o);
                o = fmaf(kh[(size_t)(2*q+1) * HW], vhi, o);
            }
            o = fmaf(kh[(size_t)50 * HW], vlast, o);
            acc[c] += o;
        }
    }

    size_t ob = (size_t)b * 3 * HW + (size_t)y * W + x;
#pragma unroll
    for (int c = 0; c < 3; c++)
        out[ob + (size_t)c * HW] = acc[c];
}

// ---------------- launch ---------------------------------------------------
extern "C" void kernel_launch(void* const* d_in, const int* in_sizes, int n_in,
                              void* d_out, int out_size)
{
    const float* x  = (const float*)d_in[0];
    const float* i1 = (const float*)d_in[1];
    const float* i2 = (const float*)d_in[2];
    const float* W1 = (const float*)d_in[3];
    const float* B1 = (const float*)d_in[4];
    const float* W2 = (const float*)d_in[5];
    const float* B2 = (const float*)d_in[6];
    const float* W3 = (const float*)d_in[7];
    const float* B3 = (const float*)d_in[8];
    float* out = (float*)d_out;

    float *u, *h1, *h2, *h3, *w1t, *w2t, *w3t;
    cudaGetSymbolAddress((void**)&u,   g_u);
    cudaGetSymbolAddress((void**)&h1,  g_h1);
    cudaGetSymbolAddress((void**)&h2,  g_h2);
    cudaGetSymbolAddress((void**)&h3,  g_h3);
    cudaGetSymbolAddress((void**)&w1t, g_w1t);
    cudaGetSymbolAddress((void**)&w2t, g_w2t);
    cudaGetSymbolAddress((void**)&w3t, g_w3t);

    {
        int n1 = NB*9*CFP*OC64, n2 = NB*9*KTP*OC64;
        wprep2_k<<<(n1 + 255)/256, 256>>>(W1, w1t, CF, CFP);
        wprep2_k<<<(n2 + 255)/256, 256>>>(W2, w2t, KT, KTP);
        wprep2_k<<<(n2 + 255)/256, 256>>>(W3, w3t, KT, KTP);
    }
    {
        int nblk = BATCH*HW/64;
        upsample_k<<<nblk, 256>>>(x);
    }

    dim3 cgrid(W/16, H/16, BATCH*NB);
    dim3 cblk(256);
    conv3x3_wmma_k<CFP, false, false><<<cgrid, cblk>>>(u,  w1t, B1, h1);
    conv3x3_wmma_k<KTP, true,  false><<<cgrid, cblk>>>(h1, w2t, B2, h2);
    conv3x3_wmma_k<KTP, true,  true ><<<cgrid, cblk>>>(h2, w3t, B3, h3);

    dim3 sgrid(W/16, H/16, BATCH);
    sepconv_k<<<sgrid, cblk>>>(i1, i2, out);

    (void)in_sizes; (void)n_in; (void)out_size;
}